// round 10
// baseline (speedup 1.0000x reference)
#include <cuda_runtime.h>
#include <cstdint>

#define NN   50000
#define NE   800000
#define DIN  96
#define DH   128
#define DOUT 16
#define RB   64          // rows per GEMM block

typedef unsigned long long ull;

// ---------------- scratch: one merged zero-init buffer [agg1 | deg | agg2] ----------------
#define OFF_AGG1 0
#define OFF_DEG  (NN * DIN)
#define OFF_AGG2 (NN * DIN + NN)
#define ZTOTAL   (NN * DIN + NN + NN * DOUT)

__device__ __align__(16) float g_zero[ZTOTAL];
__device__ __align__(16) float g_hB[NN * DH];    // x @ W1_r + b1
__device__ __align__(16) float g_r[NN * 32];     // [p | q] = h @ [W2_l | W2_r]
__device__ int g_is64;

// ---------------- f32x2 packed helpers (sm_100+) ----------------
__device__ __forceinline__ ull pk(float a, float b) {
    ull r; asm("mov.b64 %0, {%1,%2};" : "=l"(r) : "f"(a), "f"(b)); return r;
}
__device__ __forceinline__ float2 upk(ull a) {
    float2 f; asm("mov.b64 {%0,%1}, %2;" : "=f"(f.x), "=f"(f.y) : "l"(a)); return f;
}
__device__ __forceinline__ ull fma2(ull a, ull b, ull c) {
    ull d; asm("fma.rn.f32x2 %0, %1, %2, %3;" : "=l"(d) : "l"(a), "l"(b), "l"(c)); return d;
}
__device__ __forceinline__ ull add2(ull a, ull b) {
    ull d; asm("add.rn.f32x2 %0, %1, %2;" : "=l"(d) : "l"(a), "l"(b)); return d;
}
__device__ __forceinline__ ull relu2(ull a) {
    float2 f = upk(a);
    return pk(fmaxf(f.x, 0.0f), fmaxf(f.y, 0.0f));
}

// ---------------- dtype detection (parallel) ----------------
__global__ void k_detect(const int* __restrict__ ei) {
    int lane = threadIdx.x;                  // 32 threads
    int ok = (ei[2 * lane + 1] == 0) && (ei[2 * lane + 65] == 0)
          && (ei[2 * lane + 129] == 0) && (ei[2 * lane + 193] == 0);
    unsigned all = __all_sync(0xffffffffu, ok);
    if (lane == 0) g_is64 = all ? 1 : 0;
}

// ---------------- layer-1 edge aggregation + degree ----------------
__global__ void k_agg_x(const int* __restrict__ ei32,
                        const long long* __restrict__ ei64,
                        const float* __restrict__ x) {
    int gid = blockIdx.x * blockDim.x + threadIdx.x;
    if (gid >= NE * 24) return;
    int e = gid / 24;
    int c = gid - e * 24;
    int src, dst;
    if (g_is64) { src = (int)ei64[e]; dst = (int)ei64[NE + e]; }
    else        { src = ei32[e];      dst = ei32[NE + e]; }

    const float4 v = ((const float4*)(x + (size_t)src * DIN))[c];
    float4* o = ((float4*)(g_zero + OFF_AGG1 + (size_t)dst * DIN)) + c;
    asm volatile("red.global.add.v4.f32 [%0], {%1,%2,%3,%4};"
                 :: "l"(o), "f"(v.x), "f"(v.y), "f"(v.z), "f"(v.w) : "memory");
    if (c == 0) atomicAdd(&g_zero[OFF_DEG + dst], 1.0f);
}

// ---------------- independent half: g_hB = x @ W1_r + b1 (register-tiled, overlaps agg_x) ----------------
__global__ void __launch_bounds__(256) k_gemmB(
        const float* __restrict__ x,
        const float* __restrict__ W1r,
        const float* __restrict__ b1) {

    __shared__ __align__(16) float xspF[DIN * 64];   // 24 KB, swizzled

    const int tid  = threadIdx.x;
    const int row0 = blockIdx.x * RB;

    // staging: thread t -> row r = t>>2, k-chunk (t&3)*24
    {
        int r  = tid >> 2;
        int k0 = (tid & 3) * 24;
        int gnode = row0 + r;
        int q = r >> 2, lane = r & 3;
        if (gnode < NN) {
            const float* px = x + (size_t)gnode * DIN + k0;
#pragma unroll
            for (int i = 0; i < 24; i += 4) {
                float4 x4 = *(const float4*)(px + i);
#pragma unroll
                for (int kk = 0; kk < 4; kk++) {
                    int k = k0 + i + kk;
                    xspF[k * 64 + (((q + k) & 15) << 2) + lane] = ((const float*)&x4)[kk];
                }
            }
        } else {
#pragma unroll
            for (int i = 0; i < 24; i++) {
                int k = k0 + i;
                xspF[k * 64 + (((q + k) & 15) << 2) + lane] = 0.0f;
            }
        }
    }
    __syncthreads();

    const int cg = tid & 31;
    const int rg = tid >> 5;

    ull acc[4][4];
    {
        float4 b4 = *(const float4*)(b1 + 4 * cg);
#pragma unroll
        for (int c = 0; c < 4; c++) {
            float bv = ((const float*)&b4)[c];
            ull bp = pk(bv, bv);
#pragma unroll
            for (int p = 0; p < 4; p++) acc[p][c] = bp;
        }
    }

    const ulonglong2* xU2 = (const ulonglong2*)xspF;

#pragma unroll 2
    for (int k = 0; k < DIN; k++) {
        int q0 = (2 * rg + k) & 15;
        int q1 = (2 * rg + 1 + k) & 15;
        ulonglong2 x01 = xU2[k * 16 + q0];
        ulonglong2 x23 = xU2[k * 16 + q1];
        float4 wr4 = __ldg((const float4*)(W1r + k * DH + 4 * cg));
#pragma unroll
        for (int c = 0; c < 4; c++) {
            float wrv = ((const float*)&wr4)[c];
            ull wr2 = pk(wrv, wrv);
            acc[0][c] = fma2(x01.x, wr2, acc[0][c]);
            acc[1][c] = fma2(x01.y, wr2, acc[1][c]);
            acc[2][c] = fma2(x23.x, wr2, acc[2][c]);
            acc[3][c] = fma2(x23.y, wr2, acc[3][c]);
        }
    }

#pragma unroll
    for (int p = 0; p < 4; p++) {
        int r0 = row0 + 8 * rg + 2 * p;
        int r1 = r0 + 1;
        float2 f0 = upk(acc[p][0]), f1 = upk(acc[p][1]);
        float2 f2 = upk(acc[p][2]), f3 = upk(acc[p][3]);
        if (r0 < NN) *(float4*)(g_hB + (size_t)r0 * DH + 4 * cg) = make_float4(f0.x, f1.x, f2.x, f3.x);
        if (r1 < NN) *(float4*)(g_hB + (size_t)r1 * DH + 4 * cg) = make_float4(f0.y, f1.y, f2.y, f3.y);
    }
}

// ---------------- dependent half: h = relu(agg1/deg @ W1_l + hB); r = h @ [W2_l|W2_r] ----------------
__global__ void __launch_bounds__(256) k_fusedA(
        const float* __restrict__ W1l,
        const float* __restrict__ W2l,
        const float* __restrict__ W2r) {

    __shared__ __align__(16) char sm[49152];
    float* aspF = reinterpret_cast<float*>(sm);                 // [96][64]
    ull*   hsT  = reinterpret_cast<ull*>(sm);                   // [32][128]
    float* wsTk = reinterpret_cast<float*>(sm + 32768);         // [128][32]

    const int tid  = threadIdx.x;
    const int row0 = blockIdx.x * RB;

    // staging agg1/deg only
    {
        int r  = tid >> 2;
        int k0 = (tid & 3) * 24;
        int gnode = row0 + r;
        int q = r >> 2, lane = r & 3;
        if (gnode < NN) {
            float iv = 1.0f / fmaxf(g_zero[OFF_DEG + gnode], 1.0f);
            const float* pa = g_zero + OFF_AGG1 + (size_t)gnode * DIN + k0;
#pragma unroll
            for (int i = 0; i < 24; i += 4) {
                float4 a4 = *(const float4*)(pa + i);
#pragma unroll
                for (int kk = 0; kk < 4; kk++) {
                    int k = k0 + i + kk;
                    aspF[k * 64 + (((q + k) & 15) << 2) + lane] = ((const float*)&a4)[kk] * iv;
                }
            }
        } else {
#pragma unroll
            for (int i = 0; i < 24; i++) {
                int k = k0 + i;
                aspF[k * 64 + (((q + k) & 15) << 2) + lane] = 0.0f;
            }
        }
    }
    __syncthreads();

    const int cg = tid & 31;
    const int rg = tid >> 5;

    ull acc[4][4];
#pragma unroll
    for (int p = 0; p < 4; p++)
#pragma unroll
        for (int c = 0; c < 4; c++) acc[p][c] = 0;

    const ulonglong2* aU2 = (const ulonglong2*)aspF;

#pragma unroll 2
    for (int k = 0; k < DIN; k++) {
        int q0 = (2 * rg + k) & 15;
        int q1 = (2 * rg + 1 + k) & 15;
        ulonglong2 a01 = aU2[k * 16 + q0];
        ulonglong2 a23 = aU2[k * 16 + q1];
        float4 wl4 = __ldg((const float4*)(W1l + k * DH + 4 * cg));
#pragma unroll
        for (int c = 0; c < 4; c++) {
            float wlv = ((const float*)&wl4)[c];
            ull wl2 = pk(wlv, wlv);
            acc[0][c] = fma2(a01.x, wl2, acc[0][c]);
            acc[1][c] = fma2(a01.y, wl2, acc[1][c]);
            acc[2][c] = fma2(a23.x, wl2, acc[2][c]);
            acc[3][c] = fma2(a23.y, wl2, acc[3][c]);
        }
    }

    // add precomputed x@W1_r + b1
#pragma unroll
    for (int p = 0; p < 4; p++) {
        int r0 = row0 + 8 * rg + 2 * p;
        int r1 = r0 + 1;
        float4 he = (r0 < NN) ? *(const float4*)(g_hB + (size_t)r0 * DH + 4 * cg)
                              : make_float4(0.f, 0.f, 0.f, 0.f);
        float4 ho = (r1 < NN) ? *(const float4*)(g_hB + (size_t)r1 * DH + 4 * cg)
                              : make_float4(0.f, 0.f, 0.f, 0.f);
        acc[p][0] = add2(acc[p][0], pk(he.x, ho.x));
        acc[p][1] = add2(acc[p][1], pk(he.y, ho.y));
        acc[p][2] = add2(acc[p][2], pk(he.z, ho.z));
        acc[p][3] = add2(acc[p][3], pk(he.w, ho.w));
    }
    __syncthreads();   // asp reads complete before overwrite

    // relu + store packed h; load W2 (k-major)
#pragma unroll
    for (int p = 0; p < 4; p++) {
        ulonglong2* dstp = (ulonglong2*)(hsT + (size_t)(4 * rg + p) * DH + 4 * cg);
        ulonglong2 v0, v1;
        v0.x = relu2(acc[p][0]); v0.y = relu2(acc[p][1]);
        v1.x = relu2(acc[p][2]); v1.y = relu2(acc[p][3]);
        dstp[0] = v0; dstp[1] = v1;
    }
    for (int i = tid; i < DH * DOUT; i += 256) {
        int k = i >> 4, j = i & 15;
        wsTk[k * 32 + j]      = W2l[i];
        wsTk[k * 32 + 16 + j] = W2r[i];
    }
    __syncthreads();

    // stage B: thread (pg = tid>>4, c2 = tid&15): pairs {pg, pg+16}, cols {c2, c2+16}
    const int c2 = tid & 15;
    const int pg = tid >> 4;
    const ulonglong2* h0p = (const ulonglong2*)(hsT + (size_t)pg * DH);
    const ulonglong2* h1p = (const ulonglong2*)(hsT + (size_t)(pg + 16) * DH);

    ull a00 = 0, a01v = 0, a10 = 0, a11v = 0;
#pragma unroll 4
    for (int k4 = 0; k4 < DH / 4; k4++) {
        ulonglong2 hA0 = h0p[2 * k4], hA1 = h0p[2 * k4 + 1];
        ulonglong2 hB0 = h1p[2 * k4], hB1 = h1p[2 * k4 + 1];
#pragma unroll
        for (int kk = 0; kk < 4; kk++) {
            int k = 4 * k4 + kk;
            float w0 = wsTk[k * 32 + c2];
            float w1 = wsTk[k * 32 + 16 + c2];
            ull w0p = pk(w0, w0), w1p = pk(w1, w1);
            ull hA = (kk == 0) ? hA0.x : (kk == 1) ? hA0.y : (kk == 2) ? hA1.x : hA1.y;
            ull hB = (kk == 0) ? hB0.x : (kk == 1) ? hB0.y : (kk == 2) ? hB1.x : hB1.y;
            a00  = fma2(hA, w0p, a00);
            a01v = fma2(hA, w1p, a01v);
            a10  = fma2(hB, w0p, a10);
            a11v = fma2(hB, w1p, a11v);
        }
    }

    {
        int rA0 = row0 + 2 * pg,        rA1 = rA0 + 1;
        int rB0 = row0 + 2 * (pg + 16), rB1 = rB0 + 1;
        float2 f;
        f = upk(a00);
        if (rA0 < NN) g_r[(size_t)rA0 * 32 + c2] = f.x;
        if (rA1 < NN) g_r[(size_t)rA1 * 32 + c2] = f.y;
        f = upk(a01v);
        if (rA0 < NN) g_r[(size_t)rA0 * 32 + 16 + c2] = f.x;
        if (rA1 < NN) g_r[(size_t)rA1 * 32 + 16 + c2] = f.y;
        f = upk(a10);
        if (rB0 < NN) g_r[(size_t)rB0 * 32 + c2] = f.x;
        if (rB1 < NN) g_r[(size_t)rB1 * 32 + c2] = f.y;
        f = upk(a11v);
        if (rB0 < NN) g_r[(size_t)rB0 * 32 + 16 + c2] = f.x;
        if (rB1 < NN) g_r[(size_t)rB1 * 32 + 16 + c2] = f.y;
    }
}

// ---------------- layer-2 edge aggregation ----------------
__global__ void k_agg_p(const int* __restrict__ ei32,
                        const long long* __restrict__ ei64) {
    int gid = blockIdx.x * blockDim.x + threadIdx.x;
    if (gid >= NE * 4) return;
    int e = gid >> 2;
    int c = gid & 3;
    int src, dst;
    if (g_is64) { src = (int)ei64[e]; dst = (int)ei64[NE + e]; }
    else        { src = ei32[e];      dst = ei32[NE + e]; }

    const float4 v = ((const float4*)(g_r + (size_t)src * 32))[c];
    float4* o = ((float4*)(g_zero + OFF_AGG2 + (size_t)dst * DOUT)) + c;
    asm volatile("red.global.add.v4.f32 [%0], {%1,%2,%3,%4};"
                 :: "l"(o), "f"(v.x), "f"(v.y), "f"(v.z), "f"(v.w) : "memory");
}

// ---------------- epilogue: softmax(agg2/deg + b2 + q) ----------------
__global__ void k_finalize(const float* __restrict__ b2,
                           float* __restrict__ out) {
    int row = blockIdx.x * blockDim.x + threadIdx.x;
    if (row >= NN) return;
    float inv = 1.0f / fmaxf(g_zero[OFF_DEG + row], 1.0f);

    float v[DOUT];
    float mx = -1e30f;
#pragma unroll
    for (int j = 0; j < DOUT; j++) {
        v[j] = g_zero[OFF_AGG2 + (size_t)row * DOUT + j] * inv + b2[j]
             + g_r[(size_t)row * 32 + 16 + j];
        mx = fmaxf(mx, v[j]);
    }
    float s = 0.f;
#pragma unroll
    for (int j = 0; j < DOUT; j++) {
        v[j] = __expf(v[j] - mx);
        s += v[j];
    }
    float is = 1.0f / s;
#pragma unroll
    for (int j = 0; j < DOUT; j++)
        out[(size_t)row * DOUT + j] = v[j] * is;
}

// ---------------- launch ----------------
extern "C" void kernel_launch(void* const* d_in, const int* in_sizes, int n_in,
                              void* d_out, int out_size) {
    const float*     x    = (const float*)d_in[0];
    const int*       ei32 = (const int*)d_in[1];
    const long long* ei64 = (const long long*)d_in[1];
    const float*     W1l  = (const float*)d_in[2];
    const float*     b1   = (const float*)d_in[3];
    const float*     W1r  = (const float*)d_in[4];
    const float*     W2l  = (const float*)d_in[5];
    const float*     b2   = (const float*)d_in[6];
    const float*     W2r  = (const float*)d_in[7];
    float* out = (float*)d_out;

    static cudaStream_t s1 = nullptr;
    static cudaEvent_t  evFork = nullptr, evJoin = nullptr;
    if (!s1) {
        cudaStreamCreateWithFlags(&s1, cudaStreamNonBlocking);
        cudaEventCreateWithFlags(&evFork, cudaEventDisableTiming);
        cudaEventCreateWithFlags(&evJoin, cudaEventDisableTiming);
    }

    void* zp;
    cudaGetSymbolAddress(&zp, g_zero);

    // fork: independent GEMM half on side stream (overlaps memset + agg_x)
    cudaEventRecord(evFork, 0);
    cudaStreamWaitEvent(s1, evFork, 0);
    k_gemmB<<<(NN + RB - 1) / RB, 256, 0, s1>>>(x, W1r, b1);
    cudaEventRecord(evJoin, s1);

    // main stream
    cudaMemsetAsync(zp, 0, sizeof(float) * ZTOTAL, 0);
    k_detect<<<1, 32>>>(ei32);
    k_agg_x <<<(NE * 24 + 255) / 256, 256>>>(ei32, ei64, x);

    cudaStreamWaitEvent(0, evJoin, 0);
    k_fusedA  <<<(NN + RB - 1) / RB, 256>>>(W1l, W2l, W2r);
    k_agg_p   <<<(NE * 4 + 255) / 256, 256>>>(ei32, ei64);
    k_finalize<<<(NN + 127) / 128, 128>>>(b2, out);
}

// round 11
// speedup vs baseline: 1.1889x; 1.1889x over previous
#include <cuda_runtime.h>
#include <cstdint>

#define NN   50000
#define NE   800000
#define DIN  96
#define DH   128
#define DOUT 16
#define RB   64          // rows per fused block
#define EPB1 32          // edges per block, layer-1 agg
#define EPB2 64          // edges per block, layer-2 agg

typedef unsigned long long ull;

// ---------------- scratch: one merged zero-init buffer [agg1 | deg | agg2] ----------------
#define OFF_AGG1 0
#define OFF_DEG  (NN * DIN)
#define OFF_AGG2 (NN * DIN + NN)
#define ZTOTAL   (NN * DIN + NN + NN * DOUT)

__device__ __align__(16) float g_zero[ZTOTAL];
__device__ __align__(16) float g_r[NN * 32];     // [p | q] = h @ [W2_l | W2_r]
__device__ int g_is64;

// ---------------- f32x2 packed helpers (sm_100+) ----------------
__device__ __forceinline__ ull pk(float a, float b) {
    ull r; asm("mov.b64 %0, {%1,%2};" : "=l"(r) : "f"(a), "f"(b)); return r;
}
__device__ __forceinline__ float2 upk(ull a) {
    float2 f; asm("mov.b64 {%0,%1}, %2;" : "=f"(f.x), "=f"(f.y) : "l"(a)); return f;
}
__device__ __forceinline__ ull fma2(ull a, ull b, ull c) {
    ull d; asm("fma.rn.f32x2 %0, %1, %2, %3;" : "=l"(d) : "l"(a), "l"(b), "l"(c)); return d;
}
__device__ __forceinline__ ull relu2(ull a) {
    float2 f = upk(a);
    return pk(fmaxf(f.x, 0.0f), fmaxf(f.y, 0.0f));
}
__device__ __forceinline__ void red4(float* g, float4 v) {
    asm volatile("red.global.add.v4.f32 [%0], {%1,%2,%3,%4};"
                 :: "l"(g), "f"(v.x), "f"(v.y), "f"(v.z), "f"(v.w) : "memory");
}

// ---------------- dtype detection (parallel) ----------------
__global__ void k_detect(const int* __restrict__ ei) {
    int lane = threadIdx.x;                  // 32 threads
    int ok = (ei[2 * lane + 1] == 0) && (ei[2 * lane + 65] == 0)
          && (ei[2 * lane + 129] == 0) && (ei[2 * lane + 193] == 0);
    unsigned all = __all_sync(0xffffffffu, ok);
    if (lane == 0) g_is64 = all ? 1 : 0;
}

// ---------------- layer-1 edge aggregation + degree (smem-staged indices) ----------------
// 32 edges per block; indices loaded ONCE into smem (64 LDGs vs 1536),
// then 256 threads x 3 iterations cover 32 edges x 24 float4 chunks.
__global__ void __launch_bounds__(256) k_agg_x(const int* __restrict__ ei32,
                                               const long long* __restrict__ ei64,
                                               const float* __restrict__ x) {
    __shared__ int ss[EPB1], sd[EPB1];
    const int tid = threadIdx.x;
    const int e0  = blockIdx.x * EPB1;

    if (tid < EPB1) {
        int e = e0 + tid;
        int s, d;
        if (g_is64) { s = (int)ei64[e]; d = (int)ei64[NE + e]; }
        else        { s = ei32[e];      d = ei32[NE + e]; }
        ss[tid] = s;
        sd[tid] = d;
        atomicAdd(&g_zero[OFF_DEG + d], 1.0f);
    }
    __syncthreads();

#pragma unroll
    for (int i = 0; i < 3; i++) {
        int idx = i * 256 + tid;           // 0..767 = 32 edges x 24 chunks
        int e = idx / 24;
        int c = idx - e * 24;
        const float4 v = ((const float4*)(x + (size_t)ss[e] * DIN))[c];
        red4(g_zero + OFF_AGG1 + (size_t)sd[e] * DIN + 4 * c, v);
    }
}

// ---------------- fused GEMMs: 64 rows/block, register-tiled 8 rows x 4 cols (R8 champion) ----------------
__global__ void __launch_bounds__(256) k_fused(
        const float* __restrict__ x,
        const float* __restrict__ W1l,
        const float* __restrict__ b1,
        const float* __restrict__ W1r,
        const float* __restrict__ W2l,
        const float* __restrict__ W2r) {

    __shared__ __align__(16) char sm[49152];
    float* aspF = reinterpret_cast<float*>(sm);                 // [96][64]
    float* xspF = aspF + 96 * 64;                               // [96][64]
    ull*   hsT  = reinterpret_cast<ull*>(sm);                   // [32][128]
    float* wsTk = reinterpret_cast<float*>(sm + 32768);         // [128][32]

    const int tid  = threadIdx.x;
    const int row0 = blockIdx.x * RB;

    // staging: thread t -> row r = t>>2, k-chunk (t&3)*24; swizzle ull2-chunks mod 16
    {
        int r  = tid >> 2;
        int k0 = (tid & 3) * 24;
        int gnode = row0 + r;
        int q = r >> 2, lane = r & 3;
        if (gnode < NN) {
            float iv = 1.0f / fmaxf(g_zero[OFF_DEG + gnode], 1.0f);
            const float* pa = g_zero + OFF_AGG1 + (size_t)gnode * DIN + k0;
            const float* px = x + (size_t)gnode * DIN + k0;
#pragma unroll
            for (int i = 0; i < 24; i += 4) {
                float4 a4 = *(const float4*)(pa + i);
                float4 x4 = *(const float4*)(px + i);
#pragma unroll
                for (int kk = 0; kk < 4; kk++) {
                    int k = k0 + i + kk;
                    int pos = k * 64 + (((q + k) & 15) << 2) + lane;
                    aspF[pos] = ((const float*)&a4)[kk] * iv;
                    xspF[pos] = ((const float*)&x4)[kk];
                }
            }
        } else {
#pragma unroll
            for (int i = 0; i < 24; i++) {
                int k = k0 + i;
                int pos = k * 64 + (((q + k) & 15) << 2) + lane;
                aspF[pos] = 0.0f;
                xspF[pos] = 0.0f;
            }
        }
    }
    __syncthreads();

    // stage A: thread (rg = tid>>5, cg = tid&31): rows 8rg..8rg+7, cols 4cg..4cg+3
    const int cg = tid & 31;
    const int rg = tid >> 5;

    ull acc[4][4];
    {
        float4 b4 = *(const float4*)(b1 + 4 * cg);
#pragma unroll
        for (int c = 0; c < 4; c++) {
            float bv = ((const float*)&b4)[c];
            ull bp = pk(bv, bv);
#pragma unroll
            for (int p = 0; p < 4; p++) acc[p][c] = bp;
        }
    }

    const ulonglong2* aU2 = (const ulonglong2*)aspF;   // [96][16]
    const ulonglong2* xU2 = (const ulonglong2*)xspF;

#pragma unroll 2
    for (int k = 0; k < DIN; k++) {
        int q0 = (2 * rg + k) & 15;
        int q1 = (2 * rg + 1 + k) & 15;
        ulonglong2 a01 = aU2[k * 16 + q0];
        ulonglong2 a23 = aU2[k * 16 + q1];
        ulonglong2 x01 = xU2[k * 16 + q0];
        ulonglong2 x23 = xU2[k * 16 + q1];
        float4 wl4 = __ldg((const float4*)(W1l + k * DH + 4 * cg));
        float4 wr4 = __ldg((const float4*)(W1r + k * DH + 4 * cg));
#pragma unroll
        for (int c = 0; c < 4; c++) {
            float wlv = ((const float*)&wl4)[c];
            float wrv = ((const float*)&wr4)[c];
            ull wl2 = pk(wlv, wlv);
            ull wr2 = pk(wrv, wrv);
            acc[0][c] = fma2(a01.x, wl2, acc[0][c]);
            acc[0][c] = fma2(x01.x, wr2, acc[0][c]);
            acc[1][c] = fma2(a01.y, wl2, acc[1][c]);
            acc[1][c] = fma2(x01.y, wr2, acc[1][c]);
            acc[2][c] = fma2(a23.x, wl2, acc[2][c]);
            acc[2][c] = fma2(x23.x, wr2, acc[2][c]);
            acc[3][c] = fma2(a23.y, wl2, acc[3][c]);
            acc[3][c] = fma2(x23.y, wr2, acc[3][c]);
        }
    }
    __syncthreads();   // asp/xsp reads complete before phase-2 overwrite

    // relu + store h (packed pairs) + load W2 (k-major)
#pragma unroll
    for (int p = 0; p < 4; p++) {
        ulonglong2* dstp = (ulonglong2*)(hsT + (size_t)(4 * rg + p) * DH + 4 * cg);
        ulonglong2 v0, v1;
        v0.x = relu2(acc[p][0]); v0.y = relu2(acc[p][1]);
        v1.x = relu2(acc[p][2]); v1.y = relu2(acc[p][3]);
        dstp[0] = v0; dstp[1] = v1;
    }
    for (int i = tid; i < DH * DOUT; i += 256) {
        int k = i >> 4, j = i & 15;
        wsTk[k * 32 + j]      = W2l[i];
        wsTk[k * 32 + 16 + j] = W2r[i];
    }
    __syncthreads();

    // stage B: thread (pg = tid>>4, c2 = tid&15): pairs {pg, pg+16}, cols {c2, c2+16}
    const int c2 = tid & 15;
    const int pg = tid >> 4;
    const ulonglong2* h0p = (const ulonglong2*)(hsT + (size_t)pg * DH);
    const ulonglong2* h1p = (const ulonglong2*)(hsT + (size_t)(pg + 16) * DH);

    ull a00 = 0, a01v = 0, a10 = 0, a11v = 0;
#pragma unroll 4
    for (int k4 = 0; k4 < DH / 4; k4++) {
        ulonglong2 hA0 = h0p[2 * k4], hA1 = h0p[2 * k4 + 1];
        ulonglong2 hB0 = h1p[2 * k4], hB1 = h1p[2 * k4 + 1];
#pragma unroll
        for (int kk = 0; kk < 4; kk++) {
            int k = 4 * k4 + kk;
            float w0 = wsTk[k * 32 + c2];
            float w1 = wsTk[k * 32 + 16 + c2];
            ull w0p = pk(w0, w0), w1p = pk(w1, w1);
            ull hA = (kk == 0) ? hA0.x : (kk == 1) ? hA0.y : (kk == 2) ? hA1.x : hA1.y;
            ull hB = (kk == 0) ? hB0.x : (kk == 1) ? hB0.y : (kk == 2) ? hB1.x : hB1.y;
            a00  = fma2(hA, w0p, a00);
            a01v = fma2(hA, w1p, a01v);
            a10  = fma2(hB, w0p, a10);
            a11v = fma2(hB, w1p, a11v);
        }
    }

    {
        int rA0 = row0 + 2 * pg,        rA1 = rA0 + 1;
        int rB0 = row0 + 2 * (pg + 16), rB1 = rB0 + 1;
        float2 f;
        f = upk(a00);
        if (rA0 < NN) g_r[(size_t)rA0 * 32 + c2] = f.x;
        if (rA1 < NN) g_r[(size_t)rA1 * 32 + c2] = f.y;
        f = upk(a01v);
        if (rA0 < NN) g_r[(size_t)rA0 * 32 + 16 + c2] = f.x;
        if (rA1 < NN) g_r[(size_t)rA1 * 32 + 16 + c2] = f.y;
        f = upk(a10);
        if (rB0 < NN) g_r[(size_t)rB0 * 32 + c2] = f.x;
        if (rB1 < NN) g_r[(size_t)rB1 * 32 + c2] = f.y;
        f = upk(a11v);
        if (rB0 < NN) g_r[(size_t)rB0 * 32 + 16 + c2] = f.x;
        if (rB1 < NN) g_r[(size_t)rB1 * 32 + 16 + c2] = f.y;
    }
}

// ---------------- layer-2 edge aggregation (smem-staged indices) ----------------
// 64 edges per block; 128 index LDGs instead of 512.
__global__ void __launch_bounds__(256) k_agg_p(const int* __restrict__ ei32,
                                               const long long* __restrict__ ei64) {
    __shared__ int ss[EPB2], sd[EPB2];
    const int tid = threadIdx.x;
    const int e0  = blockIdx.x * EPB2;

    if (tid < EPB2) {
        int e = e0 + tid;
        int s, d;
        if (g_is64) { s = (int)ei64[e]; d = (int)ei64[NE + e]; }
        else        { s = ei32[e];      d = ei32[NE + e]; }
        ss[tid] = s;
        sd[tid] = d;
    }
    __syncthreads();

    int e = tid >> 2;
    int c = tid & 3;
    const float4 v = ((const float4*)(g_r + (size_t)ss[e] * 32))[c];   // p = first 16
    red4(g_zero + OFF_AGG2 + (size_t)sd[e] * DOUT + 4 * c, v);
}

// ---------------- epilogue: softmax(agg2/deg + b2 + q) ----------------
__global__ void k_finalize(const float* __restrict__ b2,
                           float* __restrict__ out) {
    int row = blockIdx.x * blockDim.x + threadIdx.x;
    if (row >= NN) return;
    float inv = 1.0f / fmaxf(g_zero[OFF_DEG + row], 1.0f);

    float v[DOUT];
    float mx = -1e30f;
#pragma unroll
    for (int j = 0; j < DOUT; j++) {
        v[j] = g_zero[OFF_AGG2 + (size_t)row * DOUT + j] * inv + b2[j]
             + g_r[(size_t)row * 32 + 16 + j];
        mx = fmaxf(mx, v[j]);
    }
    float s = 0.f;
#pragma unroll
    for (int j = 0; j < DOUT; j++) {
        v[j] = __expf(v[j] - mx);
        s += v[j];
    }
    float is = 1.0f / s;
#pragma unroll
    for (int j = 0; j < DOUT; j++)
        out[(size_t)row * DOUT + j] = v[j] * is;
}

// ---------------- launch ----------------
extern "C" void kernel_launch(void* const* d_in, const int* in_sizes, int n_in,
                              void* d_out, int out_size) {
    const float*     x    = (const float*)d_in[0];
    const int*       ei32 = (const int*)d_in[1];
    const long long* ei64 = (const long long*)d_in[1];
    const float*     W1l  = (const float*)d_in[2];
    const float*     b1   = (const float*)d_in[3];
    const float*     W1r  = (const float*)d_in[4];
    const float*     W2l  = (const float*)d_in[5];
    const float*     b2   = (const float*)d_in[6];
    const float*     W2r  = (const float*)d_in[7];
    float* out = (float*)d_out;

    void* zp;
    cudaGetSymbolAddress(&zp, g_zero);
    cudaMemsetAsync(zp, 0, sizeof(float) * ZTOTAL, 0);

    k_detect  <<<1, 32>>>(ei32);
    k_agg_x   <<<NE / EPB1, 256>>>(ei32, ei64, x);
    k_fused   <<<(NN + RB - 1) / RB, 256>>>(x, W1l, b1, W1r, W2l, W2r);
    k_agg_p   <<<NE / EPB2, 256>>>(ei32, ei64);
    k_finalize<<<(NN + 127) / 128, 128>>>(b2, out);
}

// round 12
// speedup vs baseline: 1.2019x; 1.0109x over previous
#include <cuda_runtime.h>
#include <cstdint>

#define NN   50000
#define NE   800000
#define DIN  96
#define DH   128
#define DOUT 16
#define RB   64          // rows per fused block
#define EPB1 64          // edges per block, layer-1 agg

typedef unsigned long long ull;

// ---------------- scratch ----------------
// g_agg1: zeroed at END of each launch (overlapped); statically zero for call 0.
__device__ __align__(16) float g_agg1[NN * DIN];
// g_small: [deg | agg2], zeroed at start (3.4 MB, ~1 us)
#define OFF_DEG  0
#define OFF_AGG2 NN
#define SMALL_TOTAL (NN + NN * DOUT)
__device__ __align__(16) float g_small[SMALL_TOTAL];
__device__ __align__(16) float g_r[NN * 32];     // [p | q] = h @ [W2_l | W2_r]
__device__ int g_is64;

// ---------------- f32x2 packed helpers (sm_100+) ----------------
__device__ __forceinline__ ull pk(float a, float b) {
    ull r; asm("mov.b64 %0, {%1,%2};" : "=l"(r) : "f"(a), "f"(b)); return r;
}
__device__ __forceinline__ float2 upk(ull a) {
    float2 f; asm("mov.b64 {%0,%1}, %2;" : "=f"(f.x), "=f"(f.y) : "l"(a)); return f;
}
__device__ __forceinline__ ull fma2(ull a, ull b, ull c) {
    ull d; asm("fma.rn.f32x2 %0, %1, %2, %3;" : "=l"(d) : "l"(a), "l"(b), "l"(c)); return d;
}
__device__ __forceinline__ ull relu2(ull a) {
    float2 f = upk(a);
    return pk(fmaxf(f.x, 0.0f), fmaxf(f.y, 0.0f));
}
__device__ __forceinline__ void red4(float* g, float4 v) {
    asm volatile("red.global.add.v4.f32 [%0], {%1,%2,%3,%4};"
                 :: "l"(g), "f"(v.x), "f"(v.y), "f"(v.z), "f"(v.w) : "memory");
}

// ---------------- dtype detection (parallel) ----------------
__global__ void k_detect(const int* __restrict__ ei) {
    int lane = threadIdx.x;                  // 32 threads
    int ok = (ei[2 * lane + 1] == 0) && (ei[2 * lane + 65] == 0)
          && (ei[2 * lane + 129] == 0) && (ei[2 * lane + 193] == 0);
    unsigned all = __all_sync(0xffffffffu, ok);
    if (lane == 0) g_is64 = all ? 1 : 0;
}

// ---------------- layer-1 edge aggregation + degree (smem-staged indices) ----------------
// 64 edges per block; 256 threads x 6 iterations cover 64 edges x 24 float4 chunks.
__global__ void __launch_bounds__(256) k_agg_x(const int* __restrict__ ei32,
                                               const long long* __restrict__ ei64,
                                               const float* __restrict__ x) {
    __shared__ int ss[EPB1], sd[EPB1];
    const int tid = threadIdx.x;
    const int e0  = blockIdx.x * EPB1;

    if (tid < EPB1) {
        int e = e0 + tid;
        int s, d;
        if (g_is64) { s = (int)ei64[e]; d = (int)ei64[NE + e]; }
        else        { s = ei32[e];      d = ei32[NE + e]; }
        ss[tid] = s;
        sd[tid] = d;
        atomicAdd(&g_small[OFF_DEG + d], 1.0f);
    }
    __syncthreads();

#pragma unroll
    for (int i = 0; i < 6; i++) {
        int idx = i * 256 + tid;           // 0..1535 = 64 edges x 24 chunks
        int e = idx / 24;
        int c = idx - e * 24;
        const float4 v = ((const float4*)(x + (size_t)ss[e] * DIN))[c];
        red4(g_agg1 + (size_t)sd[e] * DIN + 4 * c, v);
    }
}

// ---------------- fused GEMMs: 64 rows/block, register-tiled 8 rows x 4 cols ----------------
__global__ void __launch_bounds__(256) k_fused(
        const float* __restrict__ x,
        const float* __restrict__ W1l,
        const float* __restrict__ b1,
        const float* __restrict__ W1r,
        const float* __restrict__ W2l,
        const float* __restrict__ W2r) {

    __shared__ __align__(16) char sm[49152];
    float* aspF = reinterpret_cast<float*>(sm);                 // [96][64]
    float* xspF = aspF + 96 * 64;                               // [96][64]
    ull*   hsT  = reinterpret_cast<ull*>(sm);                   // [32][128]
    float* wsTk = reinterpret_cast<float*>(sm + 32768);         // [128][32]

    const int tid  = threadIdx.x;
    const int row0 = blockIdx.x * RB;

    // staging: thread t -> row r = t>>2, k-chunk (t&3)*24; swizzle ull2-chunks mod 16
    {
        int r  = tid >> 2;
        int k0 = (tid & 3) * 24;
        int gnode = row0 + r;
        int q = r >> 2, lane = r & 3;
        if (gnode < NN) {
            float iv = 1.0f / fmaxf(g_small[OFF_DEG + gnode], 1.0f);
            const float* pa = g_agg1 + (size_t)gnode * DIN + k0;
            const float* px = x + (size_t)gnode * DIN + k0;
#pragma unroll
            for (int i = 0; i < 24; i += 4) {
                float4 a4 = *(const float4*)(pa + i);
                float4 x4 = *(const float4*)(px + i);
#pragma unroll
                for (int kk = 0; kk < 4; kk++) {
                    int k = k0 + i + kk;
                    int pos = k * 64 + (((q + k) & 15) << 2) + lane;
                    aspF[pos] = ((const float*)&a4)[kk] * iv;
                    xspF[pos] = ((const float*)&x4)[kk];
                }
            }
        } else {
#pragma unroll
            for (int i = 0; i < 24; i++) {
                int k = k0 + i;
                int pos = k * 64 + (((q + k) & 15) << 2) + lane;
                aspF[pos] = 0.0f;
                xspF[pos] = 0.0f;
            }
        }
    }
    __syncthreads();

    // stage A: thread (rg = tid>>5, cg = tid&31): rows 8rg..8rg+7, cols 4cg..4cg+3
    const int cg = tid & 31;
    const int rg = tid >> 5;

    ull acc[4][4];
    {
        float4 b4 = *(const float4*)(b1 + 4 * cg);
#pragma unroll
        for (int c = 0; c < 4; c++) {
            float bv = ((const float*)&b4)[c];
            ull bp = pk(bv, bv);
#pragma unroll
            for (int p = 0; p < 4; p++) acc[p][c] = bp;
        }
    }

    const ulonglong2* aU2 = (const ulonglong2*)aspF;   // [96][16]
    const ulonglong2* xU2 = (const ulonglong2*)xspF;

#pragma unroll 2
    for (int k = 0; k < DIN; k++) {
        int q0 = (2 * rg + k) & 15;
        int q1 = (2 * rg + 1 + k) & 15;
        ulonglong2 a01 = aU2[k * 16 + q0];
        ulonglong2 a23 = aU2[k * 16 + q1];
        ulonglong2 x01 = xU2[k * 16 + q0];
        ulonglong2 x23 = xU2[k * 16 + q1];
        float4 wl4 = __ldg((const float4*)(W1l + k * DH + 4 * cg));
        float4 wr4 = __ldg((const float4*)(W1r + k * DH + 4 * cg));
#pragma unroll
        for (int c = 0; c < 4; c++) {
            float wlv = ((const float*)&wl4)[c];
            float wrv = ((const float*)&wr4)[c];
            ull wl2 = pk(wlv, wlv);
            ull wr2 = pk(wrv, wrv);
            acc[0][c] = fma2(a01.x, wl2, acc[0][c]);
            acc[0][c] = fma2(x01.x, wr2, acc[0][c]);
            acc[1][c] = fma2(a01.y, wl2, acc[1][c]);
            acc[1][c] = fma2(x01.y, wr2, acc[1][c]);
            acc[2][c] = fma2(a23.x, wl2, acc[2][c]);
            acc[2][c] = fma2(x23.x, wr2, acc[2][c]);
            acc[3][c] = fma2(a23.y, wl2, acc[3][c]);
            acc[3][c] = fma2(x23.y, wr2, acc[3][c]);
        }
    }
    __syncthreads();   // asp/xsp reads complete before phase-2 overwrite

    // relu + store h (packed pairs) + load W2 (k-major)
#pragma unroll
    for (int p = 0; p < 4; p++) {
        ulonglong2* dstp = (ulonglong2*)(hsT + (size_t)(4 * rg + p) * DH + 4 * cg);
        ulonglong2 v0, v1;
        v0.x = relu2(acc[p][0]); v0.y = relu2(acc[p][1]);
        v1.x = relu2(acc[p][2]); v1.y = relu2(acc[p][3]);
        dstp[0] = v0; dstp[1] = v1;
    }
    for (int i = tid; i < DH * DOUT; i += 256) {
        int k = i >> 4, j = i & 15;
        wsTk[k * 32 + j]      = W2l[i];
        wsTk[k * 32 + 16 + j] = W2r[i];
    }
    __syncthreads();

    // stage B: thread (pg = tid>>4, c2 = tid&15): pairs {pg, pg+16}, cols {c2, c2+16}
    const int c2 = tid & 15;
    const int pg = tid >> 4;
    const ulonglong2* h0p = (const ulonglong2*)(hsT + (size_t)pg * DH);
    const ulonglong2* h1p = (const ulonglong2*)(hsT + (size_t)(pg + 16) * DH);

    ull a00 = 0, a01v = 0, a10 = 0, a11v = 0;
#pragma unroll 4
    for (int k4 = 0; k4 < DH / 4; k4++) {
        ulonglong2 hA0 = h0p[2 * k4], hA1 = h0p[2 * k4 + 1];
        ulonglong2 hB0 = h1p[2 * k4], hB1 = h1p[2 * k4 + 1];
#pragma unroll
        for (int kk = 0; kk < 4; kk++) {
            int k = 4 * k4 + kk;
            float w0 = wsTk[k * 32 + c2];
            float w1 = wsTk[k * 32 + 16 + c2];
            ull w0p = pk(w0, w0), w1p = pk(w1, w1);
            ull hA = (kk == 0) ? hA0.x : (kk == 1) ? hA0.y : (kk == 2) ? hA1.x : hA1.y;
            ull hB = (kk == 0) ? hB0.x : (kk == 1) ? hB0.y : (kk == 2) ? hB1.x : hB1.y;
            a00  = fma2(hA, w0p, a00);
            a01v = fma2(hA, w1p, a01v);
            a10  = fma2(hB, w0p, a10);
            a11v = fma2(hB, w1p, a11v);
        }
    }

    {
        int rA0 = row0 + 2 * pg,        rA1 = rA0 + 1;
        int rB0 = row0 + 2 * (pg + 16), rB1 = rB0 + 1;
        float2 f;
        f = upk(a00);
        if (rA0 < NN) g_r[(size_t)rA0 * 32 + c2] = f.x;
        if (rA1 < NN) g_r[(size_t)rA1 * 32 + c2] = f.y;
        f = upk(a01v);
        if (rA0 < NN) g_r[(size_t)rA0 * 32 + 16 + c2] = f.x;
        if (rA1 < NN) g_r[(size_t)rA1 * 32 + 16 + c2] = f.y;
        f = upk(a10);
        if (rB0 < NN) g_r[(size_t)rB0 * 32 + c2] = f.x;
        if (rB1 < NN) g_r[(size_t)rB1 * 32 + c2] = f.y;
        f = upk(a11v);
        if (rB0 < NN) g_r[(size_t)rB0 * 32 + 16 + c2] = f.x;
        if (rB1 < NN) g_r[(size_t)rB1 * 32 + 16 + c2] = f.y;
    }
}

// ---------------- layer-2 edge aggregation (flat, R8 champion) ----------------
__global__ void k_agg_p(const int* __restrict__ ei32,
                        const long long* __restrict__ ei64) {
    int gid = blockIdx.x * blockDim.x + threadIdx.x;
    if (gid >= NE * 4) return;
    int e = gid >> 2;
    int c = gid & 3;
    int src, dst;
    if (g_is64) { src = (int)ei64[e]; dst = (int)ei64[NE + e]; }
    else        { src = ei32[e];      dst = ei32[NE + e]; }

    const float4 v = ((const float4*)(g_r + (size_t)src * 32))[c];
    red4(g_small + OFF_AGG2 + (size_t)dst * DOUT + 4 * c, v);
}

// ---------------- epilogue: softmax(agg2/deg + b2 + q) ----------------
__global__ void k_finalize(const float* __restrict__ b2,
                           float* __restrict__ out) {
    int row = blockIdx.x * blockDim.x + threadIdx.x;
    if (row >= NN) return;
    float inv = 1.0f / fmaxf(g_small[OFF_DEG + row], 1.0f);

    float v[DOUT];
    float mx = -1e30f;
#pragma unroll
    for (int j = 0; j < DOUT; j++) {
        v[j] = g_small[OFF_AGG2 + (size_t)row * DOUT + j] * inv + b2[j]
             + g_r[(size_t)row * 32 + 16 + j];
        mx = fmaxf(mx, v[j]);
    }
    float s = 0.f;
#pragma unroll
    for (int j = 0; j < DOUT; j++) {
        v[j] = __expf(v[j] - mx);
        s += v[j];
    }
    float is = 1.0f / s;
#pragma unroll
    for (int j = 0; j < DOUT; j++)
        out[(size_t)row * DOUT + j] = v[j] * is;
}

// ---------------- launch ----------------
extern "C" void kernel_launch(void* const* d_in, const int* in_sizes, int n_in,
                              void* d_out, int out_size) {
    const float*     x    = (const float*)d_in[0];
    const int*       ei32 = (const int*)d_in[1];
    const long long* ei64 = (const long long*)d_in[1];
    const float*     W1l  = (const float*)d_in[2];
    const float*     b1   = (const float*)d_in[3];
    const float*     W1r  = (const float*)d_in[4];
    const float*     W2l  = (const float*)d_in[5];
    const float*     b2   = (const float*)d_in[6];
    const float*     W2r  = (const float*)d_in[7];
    float* out = (float*)d_out;

    static cudaStream_t s1 = nullptr;
    static cudaEvent_t  evFork = nullptr, evJoin = nullptr;
    if (!s1) {
        cudaStreamCreateWithFlags(&s1, cudaStreamNonBlocking);
        cudaEventCreateWithFlags(&evFork, cudaEventDisableTiming);
        cudaEventCreateWithFlags(&evJoin, cudaEventDisableTiming);
    }

    void *smallp, *agg1p;
    cudaGetSymbolAddress(&smallp, g_small);
    cudaGetSymbolAddress(&agg1p,  g_agg1);

    // small zero (deg+agg2, 3.4 MB) + detect, then the big aggregation.
    // g_agg1 is already zero: statically on call 0, re-zeroed at end of every call.
    cudaMemsetAsync(smallp, 0, sizeof(float) * SMALL_TOTAL, 0);
    k_detect<<<1, 32>>>(ei32);
    k_agg_x <<<NE / EPB1, 256>>>(ei32, ei64, x);
    k_fused <<<(NN + RB - 1) / RB, 256>>>(x, W1l, b1, W1r, W2l, W2r);

    // fork: re-zero g_agg1 for the NEXT call, overlapped with agg_p + finalize
    cudaEventRecord(evFork, 0);
    cudaStreamWaitEvent(s1, evFork, 0);
    cudaMemsetAsync(agg1p, 0, sizeof(float) * NN * DIN, s1);
    cudaEventRecord(evJoin, s1);

    k_agg_p   <<<(NE * 4 + 255) / 256, 256>>>(ei32, ei64);
    k_finalize<<<(NN + 127) / 128, 128>>>(b2, out);

    // join: launch must not complete before the re-zero does
    cudaStreamWaitEvent(0, evJoin, 0);
}